// round 5
// baseline (speedup 1.0000x reference)
#include <cuda_runtime.h>

#define NF 27
#define FD 128
#define NPAIRS 351                    // 27*26/2
#define OUT_STRIDE (NF*FD + NPAIRS)   // 3807
#define CHUNK 32
#define PAD 36                        // keeps STS scatter conflict-free, LDS aligned

// Warp handles TWO batches. Lanes 0-15: batch A, 16-31: batch B.
// Each active sub-lane owns an 8x4 tile of the 27x27 (padded 32x28) grid:
// 16 tiles cover the upper triangle. Per k: 3x LDS.128 (12 floats) for 32 FMA.
__global__ void __launch_bounds__(128, 6)
fi_kernel(const float* __restrict__ in, float* __restrict__ out)
{
    // 4 warps x 2 batches = 8 slabs
    __shared__ float sm[8][CHUNK][PAD];

    const int w    = threadIdx.x >> 5;
    const int lane = threadIdx.x & 31;
    const int sub  = lane & 15;        // lane within batch group
    const int bsel = lane >> 4;        // 0 = batch A, 1 = batch B

    const long bbase = (long)blockIdx.x * 8 + w * 2;

    const float* __restrict__ ebA = in  + (bbase + 0) * (long)(NF * FD);
    const float* __restrict__ ebB = in  + (bbase + 1) * (long)(NF * FD);
    float*       __restrict__ obA = out + (bbase + 0) * (long)OUT_STRIDE;
    float*       __restrict__ obB = out + (bbase + 1) * (long)OUT_STRIDE;

    // sub -> (bi, bj) over the 16-tile cover of the upper triangle
    int bi, bj;
    if      (sub < 7)  { bi = 0; bj = sub;      }
    else if (sub < 12) { bi = 1; bj = sub - 5;  }   // bj 2..6
    else if (sub < 15) { bi = 2; bj = sub - 8;  }   // bj 4..6
    else               { bi = 3; bj = 6;        }

    float acc[32];
#pragma unroll
    for (int t = 0; t < 32; t++) acc[t] = 0.0f;

    float* slab = &sm[w * 2 + bsel][0][0];   // this lane's compute slab

    for (int kc = 0; kc < FD; kc += CHUNK) {
        // ---- fill: 2 batches x 7 float4 feature-groups ----
#pragma unroll
        for (int fb = 0; fb < 14; fb++) {
            const int bb = fb >> 1;            // wrong split; use explicit below
        }
        // batch A
#pragma unroll
        for (int f4 = 0; f4 < 7; f4++) {
            const int f0 = f4 * 4;
            float4 p;
            p.x = ebA[(f0 + 0) * FD + kc + lane];
            p.y = ebA[(f0 + 1) * FD + kc + lane];
            p.z = ebA[(f0 + 2) * FD + kc + lane];
            p.w = (f0 + 3 < NF) ? ebA[(f0 + 3) * FD + kc + lane] : 0.0f;
            obA[(f0 + 0) * FD + kc + lane] = p.x;
            obA[(f0 + 1) * FD + kc + lane] = p.y;
            obA[(f0 + 2) * FD + kc + lane] = p.z;
            if (f0 + 3 < NF) obA[(f0 + 3) * FD + kc + lane] = p.w;
            *reinterpret_cast<float4*>(&sm[w * 2 + 0][lane][f0]) = p;
        }
        // batch B
#pragma unroll
        for (int f4 = 0; f4 < 7; f4++) {
            const int f0 = f4 * 4;
            float4 p;
            p.x = ebB[(f0 + 0) * FD + kc + lane];
            p.y = ebB[(f0 + 1) * FD + kc + lane];
            p.z = ebB[(f0 + 2) * FD + kc + lane];
            p.w = (f0 + 3 < NF) ? ebB[(f0 + 3) * FD + kc + lane] : 0.0f;
            obB[(f0 + 0) * FD + kc + lane] = p.x;
            obB[(f0 + 1) * FD + kc + lane] = p.y;
            obB[(f0 + 2) * FD + kc + lane] = p.z;
            if (f0 + 3 < NF) obB[(f0 + 3) * FD + kc + lane] = p.w;
            *reinterpret_cast<float4*>(&sm[w * 2 + 1][lane][f0]) = p;
        }
        __syncwarp();

        // ---- compute: 8x4 tile, 3x LDS.128 + 32 FFMA per k ----
        {
            const int oi = 8 * bi, oj = 4 * bj;
#pragma unroll
            for (int kk = 0; kk < CHUNK; kk++) {
                const float* row = slab + kk * PAD;
                float4 alo = *reinterpret_cast<const float4*>(row + oi);
                float4 ahi = *reinterpret_cast<const float4*>(row + oi + 4);
                float4 c   = *reinterpret_cast<const float4*>(row + oj);
                acc[0]  += alo.x * c.x;  acc[1]  += alo.x * c.y;
                acc[2]  += alo.x * c.z;  acc[3]  += alo.x * c.w;
                acc[4]  += alo.y * c.x;  acc[5]  += alo.y * c.y;
                acc[6]  += alo.y * c.z;  acc[7]  += alo.y * c.w;
                acc[8]  += alo.z * c.x;  acc[9]  += alo.z * c.y;
                acc[10] += alo.z * c.z;  acc[11] += alo.z * c.w;
                acc[12] += alo.w * c.x;  acc[13] += alo.w * c.y;
                acc[14] += alo.w * c.z;  acc[15] += alo.w * c.w;
                acc[16] += ahi.x * c.x;  acc[17] += ahi.x * c.y;
                acc[18] += ahi.x * c.z;  acc[19] += ahi.x * c.w;
                acc[20] += ahi.y * c.x;  acc[21] += ahi.y * c.y;
                acc[22] += ahi.y * c.z;  acc[23] += ahi.y * c.w;
                acc[24] += ahi.z * c.x;  acc[25] += ahi.z * c.y;
                acc[26] += ahi.z * c.z;  acc[27] += ahi.z * c.w;
                acc[28] += ahi.w * c.x;  acc[29] += ahi.w * c.y;
                acc[30] += ahi.w * c.z;  acc[31] += ahi.w * c.w;
            }
        }
        __syncwarp();   // slab reused by next fill
    }

    // ---- epilogue: stage triu dots per batch, coalesced copy-out ----
    {
#pragma unroll
        for (int m = 0; m < 8; m++) {
#pragma unroll
            for (int n = 0; n < 4; n++) {
                int i = 8 * bi + m;
                int j = 4 * bj + n;
                if (j > i && j < NF && i < NF) {
                    int idx = (i * (53 - i)) / 2 + (j - i - 1);
                    slab[idx] = acc[m * 4 + n];   // stage in own batch slab
                }
            }
        }
    }
    __syncwarp();

    float* ointA = obA + NF * FD;
    float* ointB = obB + NF * FD;
    const float* stA = &sm[w * 2 + 0][0][0];
    const float* stB = &sm[w * 2 + 1][0][0];
#pragma unroll
    for (int t = 0; t < 11; t++) {
        int idx = t * 32 + lane;
        if (idx < NPAIRS) {
            ointA[idx] = stA[idx];
            ointB[idx] = stB[idx];
        }
    }
}

extern "C" void kernel_launch(void* const* d_in, const int* in_sizes, int n_in,
                              void* d_out, int out_size)
{
    const float* in = (const float*)d_in[0];
    float* out = (float*)d_out;
    const int B = in_sizes[0] / (NF * FD);   // 16384
    fi_kernel<<<B / 8, 128>>>(in, out);
}

// round 6
// speedup vs baseline: 1.1004x; 1.1004x over previous
#include <cuda_runtime.h>
#include <cstdint>

#define NF 27
#define FD 128
#define NPAIRS 351                    // 27*26/2
#define OUT_STRIDE (NF*FD + NPAIRS)   // 3807
#define CHUNK 32
#define PAD 36                        // conflict-free STS.128 scatter, 16B-aligned rows

// acc_pair += (a,a) * (c_lo,c_hi)  — packed f32x2 FFMA (1 issue slot for 2 FMA)
#define FFMA2(accp, adup, cpair) \
    asm("fma.rn.f32x2 %0, %1, %2, %0;" : "+l"(accp) : "l"(adup), "l"(cpair))
#define DUP_F32X2(dst, f) \
    asm("mov.b64 %0, {%1, %1};" : "=l"(dst) : "f"(f))
#define UNPACK_F32X2P(lo, hi, p) \
    asm("mov.b64 {%0, %1}, %2;" : "=f"(lo), "=f"(hi) : "l"(p))

// Warp-per-batch feature interaction (R4 memory layout + FFMA2 + higher occupancy).
__global__ void __launch_bounds__(128, 9)
fi_kernel(const float* __restrict__ in, float* __restrict__ out)
{
    __shared__ float sm[4][CHUNK][PAD];

    const int w    = threadIdx.x >> 5;
    const int lane = threadIdx.x & 31;
    const long b   = (long)blockIdx.x * 4 + w;

    const float* __restrict__ eb = in  + b * (long)(NF * FD);
    float*       __restrict__ ob = out + b * (long)OUT_STRIDE;

    // lane -> (gi, gj): 28 upper (incl diag) 4x4 blocks of the 7x7 group grid
    int gi = 0, rem = lane;
    while (gi < 6 && rem >= 7 - gi) { rem -= 7 - gi; gi++; }
    const int gj = gi + rem;
    const bool active = (lane < 28);

    // accp[2*m+p]: packed pair (acc[m][2p], acc[m][2p+1])
    unsigned long long accp[8];
#pragma unroll
    for (int t = 0; t < 8; t++) accp[t] = 0ULL;

    for (int kc = 0; kc < FD; kc += CHUNK) {
        // ---- fill: 7 x (4 coalesced LDG.32 + 4 STG.32 + 1 STS.128) ----
#pragma unroll
        for (int f4 = 0; f4 < 7; f4++) {
            const int f0 = f4 * 4;
            float4 p;
            p.x = eb[(f0 + 0) * FD + kc + lane];
            p.y = eb[(f0 + 1) * FD + kc + lane];
            p.z = eb[(f0 + 2) * FD + kc + lane];
            p.w = (f0 + 3 < NF) ? eb[(f0 + 3) * FD + kc + lane] : 0.0f;

            ob[(f0 + 0) * FD + kc + lane] = p.x;
            ob[(f0 + 1) * FD + kc + lane] = p.y;
            ob[(f0 + 2) * FD + kc + lane] = p.z;
            if (f0 + 3 < NF) ob[(f0 + 3) * FD + kc + lane] = p.w;

            *reinterpret_cast<float4*>(&sm[w][lane][f0]) = p;   // conflict-free
        }
        __syncwarp();

        // ---- compute: per k: 2x LDS.128 + 4x mov.b64 + 8x fma.rn.f32x2 ----
        if (active) {
            const float* base = &sm[w][0][0];
            const int oi = 4 * gi, oj = 4 * gj;
#pragma unroll
            for (int kk = 0; kk < CHUNK; kk++) {
                const float* row = base + kk * PAD;
                float4 a = *reinterpret_cast<const float4*>(row + oi);
                ulonglong2 c = *reinterpret_cast<const ulonglong2*>(row + oj);
                unsigned long long ax, ay, az, aw;
                DUP_F32X2(ax, a.x);
                DUP_F32X2(ay, a.y);
                DUP_F32X2(az, a.z);
                DUP_F32X2(aw, a.w);
                FFMA2(accp[0], ax, c.x);  FFMA2(accp[1], ax, c.y);
                FFMA2(accp[2], ay, c.x);  FFMA2(accp[3], ay, c.y);
                FFMA2(accp[4], az, c.x);  FFMA2(accp[5], az, c.y);
                FFMA2(accp[6], aw, c.x);  FFMA2(accp[7], aw, c.y);
            }
        }
        __syncwarp();   // smem reused by next fill
    }

    // ---- epilogue: unpack + stage triu dots in smem, coalesced copy-out ----
    float* stage = &sm[w][0][0];
    if (active) {
#pragma unroll
        for (int m = 0; m < 4; m++) {
#pragma unroll
            for (int p = 0; p < 2; p++) {
                float lo, hi;
                UNPACK_F32X2P(lo, hi, accp[2 * m + p]);
                int i = 4 * gi + m;
#pragma unroll
                for (int q = 0; q < 2; q++) {
                    int j = 4 * gj + 2 * p + q;
                    float v = q ? hi : lo;
                    if (j > i && j < NF && i < NF) {
                        int idx = (i * (53 - i)) / 2 + (j - i - 1);
                        stage[idx] = v;
                    }
                }
            }
        }
    }
    __syncwarp();

    float* oint = ob + NF * FD;
#pragma unroll
    for (int t = 0; t < 11; t++) {
        int idx = t * 32 + lane;
        if (idx < NPAIRS) oint[idx] = stage[idx];
    }
}

extern "C" void kernel_launch(void* const* d_in, const int* in_sizes, int n_in,
                              void* d_out, int out_size)
{
    const float* in = (const float*)d_in[0];
    float* out = (float*)d_out;
    const int B = in_sizes[0] / (NF * FD);   // 16384
    fi_kernel<<<B / 4, 128>>>(in, out);
}

// round 9
// speedup vs baseline: 1.2514x; 1.1373x over previous
#include <cuda_runtime.h>
#include <cuda_bf16.h>
#include <cstdint>

#define NF 27
#define FD 128
#define NPAIRS 351
#define OUT_STRIDE (NF*FD + NPAIRS)   // 3807 (odd -> out rows only 4B-aligned!)
#define CHUNK 32
#define ROWB 80                        // 32 bf16 (64B) + 16B pad; ldmatrix conflict-free
#define TILEB (32 * ROWB)              // 2560 B per tile

__device__ __forceinline__ uint32_t smem_u32(const void* p) {
    uint32_t a;
    asm("{ .reg .u64 t; cvta.to.shared.u64 t, %1; cvt.u32.u64 %0, t; }" : "=r"(a) : "l"(p));
    return a;
}

#define LDSM4(q, addr) \
    asm volatile("ldmatrix.sync.aligned.m8n8.x4.shared.b16 {%0,%1,%2,%3}, [%4];" \
                 : "=r"((q)[0]), "=r"((q)[1]), "=r"((q)[2]), "=r"((q)[3]) : "r"(addr))

#define MMA(accv, a0, a1, b) \
    asm volatile("mma.sync.aligned.m16n8k8.row.col.f32.bf16.bf16.f32 " \
                 "{%0,%1,%2,%3}, {%4,%5}, {%6}, {%0,%1,%2,%3};" \
                 : "+f"((accv)[0]), "+f"((accv)[1]), "+f"((accv)[2]), "+f"((accv)[3]) \
                 : "r"(a0), "r"(a1), "r"(b))

// Warp-per-batch Gram via mma.sync bf16 (hi/lo split, 3 passes, fp32 accum).
__global__ void __launch_bounds__(128, 6)
fi_kernel(const float* __restrict__ in, float* __restrict__ out)
{
    __shared__ __align__(16) char smem[4 * 2 * TILEB];   // per warp: hi tile, lo tile

    const int w    = threadIdx.x >> 5;
    const int lane = threadIdx.x & 31;
    const long b   = (long)blockIdx.x * 4 + w;

    const float* __restrict__ eb = in  + b * (long)(NF * FD);
    float*       __restrict__ ob = out + b * (long)OUT_STRIDE;

    char* hit = smem + w * 2 * TILEB;
    char* lot = hit + TILEB;
    const uint32_t hib = smem_u32(hit);
    const uint32_t lob = smem_u32(lot);

    // zero pad rows 27..31 once
    for (int idx = lane; idx < (5 * ROWB) / 4; idx += 32) {
        reinterpret_cast<uint32_t*>(hit + 27 * ROWB)[idx] = 0;
        reinterpret_cast<uint32_t*>(lot + 27 * ROWB)[idx] = 0;
    }

    float acc[8][4];
#pragma unroll
    for (int t = 0; t < 8; t++)
#pragma unroll
        for (int e = 0; e < 4; e++) acc[t][e] = 0.0f;

    const int half = lane >> 4;        // which feature of the pair
    const int ks   = lane & 15;        // k-pair index within chunk

    for (int kc = 0; kc < FD; kc += CHUNK) {
        // ---- fill: 14 x (LDG.64 + 2x STG.32 copy + hi/lo cvt + 2x STS.32) ----
#pragma unroll
        for (int it = 0; it < 14; it++) {
            const int f = 2 * it + half;
            float2 v = make_float2(0.0f, 0.0f);
            if (f < NF) {
                v = *reinterpret_cast<const float2*>(eb + f * FD + kc + 2 * ks);
                // out rows are only 4B-aligned (stride 3807) -> scalar stores
                ob[f * FD + kc + 2 * ks]     = v.x;
                ob[f * FD + kc + 2 * ks + 1] = v.y;
            }
            __nv_bfloat16 h0 = __float2bfloat16(v.x);
            __nv_bfloat16 h1 = __float2bfloat16(v.y);
            float r0 = v.x - __bfloat162float(h0);
            float r1 = v.y - __bfloat162float(h1);
            __nv_bfloat162 hp = __halves2bfloat162(h0, h1);
            __nv_bfloat162 lp = __halves2bfloat162(__float2bfloat16(r0),
                                                   __float2bfloat16(r1));
            const int fr = (f < 28) ? f : 27;   // f==27 writes zeros (harmless)
            *reinterpret_cast<uint32_t*>(hit + fr * ROWB + 4 * ks) =
                *reinterpret_cast<uint32_t*>(&hp);
            *reinterpret_cast<uint32_t*>(lot + fr * ROWB + 4 * ks) =
                *reinterpret_cast<uint32_t*>(&lp);
        }
        __syncwarp();

        // ---- compute: 2 k16 units per chunk ----
#pragma unroll
        for (int kk = 0; kk < 2; kk++) {
            const uint32_t boff = (uint32_t)((lane & 15) * ROWB + kk * 32
                                             + (lane >> 4) * 16);
            uint32_t qh0[4], qh1[4], ql0[4], ql1[4];
            LDSM4(qh0, hib + boff);                   // rows 0-15  (hi)
            LDSM4(qh1, hib + boff + 16 * ROWB);       // rows 16-31 (hi)
            LDSM4(ql0, lob + boff);                   // rows 0-15  (lo)
            LDSM4(ql1, lob + boff + 16 * ROWB);       // rows 16-31 (lo)

#pragma unroll
            for (int kstep = 0; kstep < 2; kstep++) {
#pragma unroll
                for (int m = 0; m < 2; m++) {
                    const uint32_t* qh = m ? qh1 : qh0;
                    const uint32_t* ql = m ? ql1 : ql0;
                    const uint32_t Ah0 = qh[2 * kstep], Ah1 = qh[2 * kstep + 1];
                    const uint32_t Al0 = ql[2 * kstep], Al1 = ql[2 * kstep + 1];
#pragma unroll
                    for (int g = 0; g < 4; g++) {
                        const uint32_t Bh = (g < 2 ? qh0 : qh1)[2 * kstep + (g & 1)];
                        const uint32_t Bl = (g < 2 ? ql0 : ql1)[2 * kstep + (g & 1)];
                        MMA(acc[m * 4 + g], Ah0, Ah1, Bh);   // hi*hi
                        MMA(acc[m * 4 + g], Ah0, Ah1, Bl);   // hi*lo
                        MMA(acc[m * 4 + g], Al0, Al1, Bh);   // lo*hi
                    }
                }
            }
        }
        __syncwarp();   // tile reused by next chunk's fill
    }

    // ---- epilogue: scatter triu dots into smem stage, coalesced copy-out ----
    float* stage = reinterpret_cast<float*>(hit);   // tile no longer needed
    {
        const int r4 = lane >> 2;
        const int c2 = 2 * (lane & 3);
#pragma unroll
        for (int m = 0; m < 2; m++) {
#pragma unroll
            for (int g = 0; g < 4; g++) {
#pragma unroll
                for (int e = 0; e < 4; e++) {
                    const int i = 16 * m + r4 + ((e >= 2) ? 8 : 0);
                    const int j = 8 * g + c2 + (e & 1);
                    if (j > i && j < NF) {
                        stage[(i * (53 - i)) / 2 + (j - i - 1)] = acc[m * 4 + g][e];
                    }
                }
            }
        }
    }
    __syncwarp();

    float* oint = ob + NF * FD;
#pragma unroll
    for (int t = 0; t < 11; t++) {
        const int idx = t * 32 + lane;
        if (idx < NPAIRS) oint[idx] = stage[idx];
    }
}

extern "C" void kernel_launch(void* const* d_in, const int* in_sizes, int n_in,
                              void* d_out, int out_size)
{
    const float* in = (const float*)d_in[0];
    float* out = (float*)d_out;
    const int B = in_sizes[0] / (NF * FD);   // 16384
    fi_kernel<<<B / 4, 128>>>(in, out);
}